// round 7
// baseline (speedup 1.0000x reference)
#include <cuda_runtime.h>
#include <math.h>

// GenomicLogicBraidIntegrator — warp-per-block, antisymmetry-reduced.
//
// r2[j] in {0, sc*e1, sc*e2, sc*e3} -> segment descriptor g=(idx[j],idx[j+1]).
// term for (b,a) = -term for (a,b) (dr2 flips, m2 same); diagonal terms = 0.
// So the O(N^2) Gauss linking sum collapses EXACTLY to
//     sum_{p in 6 unordered pairs} (cnt[a,b]-cnt[b,a]) * S[p],
//     S[p] = sum_i term(i, p)
// cnt depends only on idx, S only on bytes -> no dependency, fully parallel.
// Grid 128x32: one warp per block (no smem, no bar.sync), shuffles only.

#define EPSF 1e-9f
#define NBLK 128
#define NTHR 32

__device__ float        g_S[NBLK * 6];    // per-block S[p] partials
__device__ int          g_E[NBLK * 6];    // per-block eff-count partials
__device__ unsigned int g_ticket = 0;

__global__ void __launch_bounds__(NTHR)
braid_kernel(const float* __restrict__ bytes,
             const int*   __restrict__ idx,
             int n, float* __restrict__ out)
{
    const int lane = threadIdx.x;
    const int nseg = n - 1;                       // 4095
    const int i    = blockIdx.x * NTHR + lane;    // this thread's segment
    const bool act = (i < nseg);

    // ---- all global loads up front --------------------------------------
    int   ia = act ? idx[i]       : 0;
    int   ib = act ? idx[i + 1]   : 0;
    float b0 = act ? bytes[i]     : 0.0f;
    float b1 = act ? bytes[i + 1] : 0.0f;

    // ---- effective count side: signed contribution to one of 6 pairs ----
    int e[6];
    #pragma unroll
    for (int p = 0; p < 6; p++) e[p] = 0;
    if (act && ia != ib) {
        int a = min(ia, ib), b = max(ia, ib);
        int p = a * (7 - a) / 2 + b - a - 1;      // (0,1)->0 .. (2,3)->5
        int s = (ia < ib) ? 1 : -1;
        #pragma unroll
        for (int q = 0; q < 6; q++) if (q == p) e[q] = s;
    }

    // ---- term side: contribution to each of the 6 pair sums --------------
    float term[6];
    {
        const float TWO_PI = 6.283185307179586476925f;
        float t0 = (b0 / 255.0f) * TWO_PI;
        float t1 = (b1 / 255.0f) * TWO_PI;
        float s0, c0, s1, c1;
        sincosf(t0, &s0, &c0);
        sincosf(t1, &s1, &c1);

        float x0 = 0.5f * s0, y0 = 0.3f * s0, z0 = 0.2f * s0;
        float x1 = 0.5f * s1, y1 = 0.3f * s1, z1 = 0.2f * s1;
        float inv0 = rsqrtf(c0 * c0 + x0 * x0 + y0 * y0 + z0 * z0 + EPSF);
        float inv1 = rsqrtf(c1 * c1 + x1 * x1 + y1 * y1 + z1 * z1 + EPSF);
        x0 *= inv0; y0 *= inv0; z0 *= inv0;
        x1 *= inv1; y1 *= inv1; z1 *= inv1;

        float dx1 = x1 - x0, dy1 = y1 - y0, dz1 = z1 - z0;
        float mx1 = 0.5f * (x1 + x0), my1 = 0.5f * (y1 + y0), mz1 = 0.5f * (z1 + z0);

        const float sc = 1.0f / sqrtf(1.0f + EPSF);  // normalize(e_v) comp
        // pair tables (a<b): (0,1)(0,2)(0,3)(1,2)(1,3)(2,3)
        const float AX[6] = { sc, 0.f, 0.f, -sc, -sc,  0.f };
        const float AY[6] = { 0.f, sc, 0.f,  sc, 0.f, -sc  };
        const float AZ[6] = { 0.f, 0.f, sc,  0.f, sc,  sc  };
        const float OX[6] = { sc*0.5f, 0.f, 0.f, sc*0.5f, sc*0.5f, 0.f };
        const float OY[6] = { 0.f, sc*0.5f, 0.f, sc*0.5f, 0.f, sc*0.5f };
        const float OZ[6] = { 0.f, 0.f, sc*0.5f, 0.f, sc*0.5f, sc*0.5f };

        #pragma unroll
        for (int p = 0; p < 6; p++) {
            float ax = AX[p], ay = AY[p], az = AZ[p];
            float cx = dy1 * az - dz1 * ay;
            float cy = dz1 * ax - dx1 * az;
            float cz = dx1 * ay - dy1 * ax;
            float fx = mx1 - OX[p], fy = my1 - OY[p], fz = mz1 - OZ[p];
            float num = cx * fx + cy * fy + cz * fz;
            float d2  = fx * fx + fy * fy + fz * fz + EPSF;
            float rin = rsqrtf(d2);                   // d2^-1.5 = rin^3
            term[p] = act ? (num * (rin * rin * rin)) : 0.0f;
        }
    }

    // ---- warp tree reduction (floats + ints), deterministic --------------
    #pragma unroll
    for (int off = 16; off > 0; off >>= 1) {
        #pragma unroll
        for (int p = 0; p < 6; p++) {
            term[p] += __shfl_down_sync(0xffffffffu, term[p], off);
            e[p]    += __shfl_down_sync(0xffffffffu, e[p],    off);
        }
    }

    if (lane == 0) {
        #pragma unroll
        for (int p = 0; p < 6; p++) {
            g_S[blockIdx.x * 6 + p] = term[p];
            g_E[blockIdx.x * 6 + p] = e[p];
        }
    }

    // ---- fenced ticket ----------------------------------------------------
    unsigned int tkt = 0;
    if (lane == 0) {
        __threadfence();
        tkt = atomicInc(&g_ticket, NBLK - 1);   // wraps -> graph-replayable
    }
    tkt = __shfl_sync(0xffffffffu, tkt, 0);
    if (tkt != NBLK - 1) return;

    // ---- last block: fixed-order fold of 128 partials --------------------
    __threadfence();    // acquire side
    double total = 0.0;
    #pragma unroll
    for (int p = 0; p < 6; p++) {
        // lane l sums blocks l, l+32, l+64, l+96 (deterministic), then tree
        double s = 0.0;
        int    c = 0;
        #pragma unroll
        for (int w = 0; w < NBLK / 32; w++) {
            int b = lane + w * 32;
            s += (double)g_S[b * 6 + p];
            c += g_E[b * 6 + p];
        }
        #pragma unroll
        for (int off = 16; off > 0; off >>= 1) {
            s += __shfl_down_sync(0xffffffffu, s, off);
            c += __shfl_down_sync(0xffffffffu, c, off);
        }
        total += (double)c * s;    // only lane 0's value is used
    }
    if (lane == 0)
        out[0] = (float)(total / (4.0 * 3.14159265358979323846));
}

extern "C" void kernel_launch(void* const* d_in, const int* in_sizes, int n_in,
                              void* d_out, int out_size)
{
    const float* bytes = (const float*)d_in[0];   // starcoder_bytes, 4096 f32
    const int*   idx   = (const int*)d_in[1];     // hg38_indices,   4096 i32
    float*       out   = (float*)d_out;

    int n = in_sizes[0];   // 4096

    braid_kernel<<<NBLK, NTHR>>>(bytes, idx, n, out);
}

// round 8
// speedup vs baseline: 1.6978x; 1.6978x over previous
#include <cuda_runtime.h>
#include <math.h>

// GenomicLogicBraidIntegrator — 32x128, antisymmetry-reduced, REDUX-packed.
//
// r2[j] in {0, sc*e1, sc*e2, sc*e3} -> descriptor (idx[j], idx[j+1]).
// term(b,a) = -term(a,b) (dr2 flips, m2 same); diagonal terms = 0. So
//   result = sum_{p in 6 unordered pairs} (cnt[a,b]-cnt[b,a]) * S[p],
//   S[p] = sum_i term(i,p)
// cnt depends only on idx, S only on bytes -> computed concurrently.
// Signed counts ride in 10-bit biased fields of two u32s, reduced with
// __reduce_add_sync (2 instr replaces 30 shuffles).

#define EPSF 1e-9f
#define NBLK 32
#define NTHR 128
#define BIAS 16          // per-thread per-field bias; warp sum = 512 +/- 32

__device__ float        g_S[6 * NBLK];    // [pair][block] S partials
__device__ int          g_E[6 * NBLK];    // [pair][block] signed counts
__device__ unsigned int g_ticket = 0;

__global__ void __launch_bounds__(NTHR)
braid_kernel(const float* __restrict__ bytes,
             const int*   __restrict__ idx,
             int n, float* __restrict__ out)
{
    const int tid  = threadIdx.x;
    const int lane = tid & 31;
    const int wid  = tid >> 5;
    const int nseg = n - 1;                       // 4095
    const int i    = blockIdx.x * NTHR + tid;     // this thread's segment
    const bool act = (i < nseg);

    // ---- all global loads up front ---------------------------------------
    int   ia = act ? idx[i]       : 0;
    int   ib = act ? idx[i + 1]   : 0;
    float b0 = act ? bytes[i]     : 0.0f;
    float b1 = act ? bytes[i + 1] : 0.0f;

    // ---- signed pair count, packed: pack0 fields p=0..2, pack1 p=3..5 ----
    // field value = BIAS + e_p, e_p in {-1,0,+1}; exactly one nonzero.
    unsigned int pack0 = BIAS | (BIAS << 10) | (BIAS << 20);
    unsigned int pack1 = pack0;
    if (act && ia != ib) {
        int a = min(ia, ib), b = max(ia, ib);
        int p = a * (7 - a) / 2 + b - a - 1;      // (0,1)->0 .. (2,3)->5
        int s = (ia < ib) ? 1 : -1;
        if (p < 3) pack0 += (unsigned int)s << (p * 10);
        else       pack1 += (unsigned int)s << ((p - 3) * 10);
    }
    pack0 = __reduce_add_sync(0xffffffffu, pack0);   // per-field: 512 +/- 32
    pack1 = __reduce_add_sync(0xffffffffu, pack1);

    // ---- term side: contribution to each of the 6 pair sums --------------
    float term[6];
    {
        const float TWO_PI = 6.283185307179586476925f;
        float t0 = (b0 / 255.0f) * TWO_PI;
        float t1 = (b1 / 255.0f) * TWO_PI;
        float s0, c0, s1, c1;
        sincosf(t0, &s0, &c0);
        sincosf(t1, &s1, &c1);

        float x0 = 0.5f * s0, y0 = 0.3f * s0, z0 = 0.2f * s0;
        float x1 = 0.5f * s1, y1 = 0.3f * s1, z1 = 0.2f * s1;
        float inv0 = rsqrtf(c0 * c0 + x0 * x0 + y0 * y0 + z0 * z0 + EPSF);
        float inv1 = rsqrtf(c1 * c1 + x1 * x1 + y1 * y1 + z1 * z1 + EPSF);
        x0 *= inv0; y0 *= inv0; z0 *= inv0;
        x1 *= inv1; y1 *= inv1; z1 *= inv1;

        float dx1 = x1 - x0, dy1 = y1 - y0, dz1 = z1 - z0;
        float mx1 = 0.5f * (x1 + x0), my1 = 0.5f * (y1 + y0), mz1 = 0.5f * (z1 + z0);

        const float sc = 1.0f / sqrtf(1.0f + EPSF);  // normalize(e_v) comp
        // pair tables (a<b): (0,1)(0,2)(0,3)(1,2)(1,3)(2,3) — constant-folded
        const float AX[6] = { sc, 0.f, 0.f, -sc, -sc,  0.f };
        const float AY[6] = { 0.f, sc, 0.f,  sc, 0.f, -sc  };
        const float AZ[6] = { 0.f, 0.f, sc,  0.f, sc,  sc  };
        const float OX[6] = { sc*0.5f, 0.f, 0.f, sc*0.5f, sc*0.5f, 0.f };
        const float OY[6] = { 0.f, sc*0.5f, 0.f, sc*0.5f, 0.f, sc*0.5f };
        const float OZ[6] = { 0.f, 0.f, sc*0.5f, 0.f, sc*0.5f, sc*0.5f };

        #pragma unroll
        for (int p = 0; p < 6; p++) {
            float cx = dy1 * AZ[p] - dz1 * AY[p];
            float cy = dz1 * AX[p] - dx1 * AZ[p];
            float cz = dx1 * AY[p] - dy1 * AX[p];
            float fx = mx1 - OX[p], fy = my1 - OY[p], fz = mz1 - OZ[p];
            float num = cx * fx + cy * fy + cz * fz;
            float d2  = fx * fx + fy * fy + fz * fz + EPSF;
            float rin = rsqrtf(d2);                   // d2^-1.5 = rin^3
            term[p] = act ? (num * (rin * rin * rin)) : 0.0f;
        }
    }

    // ---- warp tree reduction of the 6 floats ------------------------------
    #pragma unroll
    for (int off = 16; off > 0; off >>= 1) {
        #pragma unroll
        for (int p = 0; p < 6; p++)
            term[p] += __shfl_down_sync(0xffffffffu, term[p], off);
    }

    // ---- block combine (4 warps) ------------------------------------------
    __shared__ float        s_S[4][6];
    __shared__ unsigned int s_P[4][2];
    if (lane == 0) {
        #pragma unroll
        for (int p = 0; p < 6; p++) s_S[wid][p] = term[p];
        s_P[wid][0] = pack0; s_P[wid][1] = pack1;
    }
    __syncthreads();

    if (tid < 6) {
        float S = s_S[0][tid] + s_S[1][tid] + s_S[2][tid] + s_S[3][tid];
        int sh = (tid < 3) ? tid * 10 : (tid - 3) * 10;
        int q  = (tid < 3) ? 0 : 1;
        int E  = 0;
        #pragma unroll
        for (int w = 0; w < 4; w++)
            E += (int)((s_P[w][q] >> sh) & 1023u) - 32 * BIAS;
        g_S[tid * NBLK + blockIdx.x] = S;
        g_E[tid * NBLK + blockIdx.x] = E;
    }

    // ---- fenced ticket -----------------------------------------------------
    __shared__ bool amLast;
    __syncthreads();
    if (tid == 0) {
        __threadfence();
        unsigned int t = atomicInc(&g_ticket, NBLK - 1);  // wraps -> replayable
        amLast = (t == NBLK - 1);
    }
    __syncthreads();

    // ---- last block, first warp: fixed-order fold of 32 partials ----------
    if (amLast && tid < 32) {
        float Sp[6];
        int   Ep[6];
        #pragma unroll
        for (int p = 0; p < 6; p++) {
            Sp[p] = g_S[p * NBLK + tid];                 // coalesced
            Ep[p] = __reduce_add_sync(0xffffffffu, g_E[p * NBLK + tid]);
        }
        #pragma unroll
        for (int off = 16; off > 0; off >>= 1) {
            #pragma unroll
            for (int p = 0; p < 6; p++)
                Sp[p] += __shfl_down_sync(0xffffffffu, Sp[p], off);
        }
        if (tid == 0) {
            double total = 0.0;
            #pragma unroll
            for (int p = 0; p < 6; p++)
                total += (double)Ep[p] * (double)Sp[p];
            out[0] = (float)(total / (4.0 * 3.14159265358979323846));
        }
    }
}

extern "C" void kernel_launch(void* const* d_in, const int* in_sizes, int n_in,
                              void* d_out, int out_size)
{
    const float* bytes = (const float*)d_in[0];   // starcoder_bytes, 4096 f32
    const int*   idx   = (const int*)d_in[1];     // hg38_indices,   4096 i32
    float*       out   = (float*)d_out;

    int n = in_sizes[0];   // 4096

    braid_kernel<<<NBLK, NTHR>>>(bytes, idx, n, out);
}